// round 3
// baseline (speedup 1.0000x reference)
#include <cuda_runtime.h>
#include <cuda_bf16.h>

#define N_NODES 50000
#define NFEAT   256
#define NHID    128
#define LATENT  64

// ---------------- scratch (no allocations allowed) ----------------
__device__ float g_hpre[(size_t)N_NODES * NHID];   // x@W1 (pre-aggregation messages, layer 1)
__device__ float g_agg [(size_t)N_NODES * NHID];   // aggregation target (reused for both layers)
__device__ float g_hz  [(size_t)N_NODES * NHID];   // h@[Wmu|Wlv] (pre-aggregation, layer 2)
__device__ float g_wcat[NHID * NHID];              // [Wmu | Wlv] packed, 128x128

// ---------------- zero fill ----------------
__global__ void zero_kernel(float4* p, int n4) {
    int i = blockIdx.x * blockDim.x + threadIdx.x;
    if (i < n4) p[i] = make_float4(0.f, 0.f, 0.f, 0.f);
}

// ---------------- pack [Wmu | Wlv] into 128x128 ----------------
__global__ void pack_wcat(const float* __restrict__ Wmu, const float* __restrict__ Wlv,
                          float* __restrict__ Wcat) {
    int i = blockIdx.x * blockDim.x + threadIdx.x;   // 0..16383
    if (i >= NHID * NHID) return;
    int k = i >> 7, n = i & 127;
    Wcat[i] = (n < LATENT) ? Wmu[k * LATENT + n] : Wlv[k * LATENT + (n - LATENT)];
}

// ---------------- tiled fp32 GEMM: C[M,128] = op(A[M,K]) @ B[K,128] ----------------
// If bias != nullptr, the A operand is read as relu(A[m,k] + bias[k])  (fused layer-1 activation).
#define BM 128
#define BN 128
#define BK 16

__global__ __launch_bounds__(256) void gemm_bias_relu(
    const float* __restrict__ A, const float* __restrict__ B, float* __restrict__ C,
    int M, int K, const float* __restrict__ bias)
{
    __shared__ __align__(16) float As[BK][BM];  // transposed: As[k][m]
    __shared__ __align__(16) float Bs[BK][BN];

    const int m0  = blockIdx.x * BM;
    const int tid = threadIdx.x;
    const int ty  = tid >> 4;    // 0..15 -> row group
    const int tx  = tid & 15;    // 0..15 -> col group

    float acc[8][8];
    #pragma unroll
    for (int i = 0; i < 8; i++)
        #pragma unroll
        for (int j = 0; j < 8; j++) acc[i][j] = 0.f;

    for (int k0 = 0; k0 < K; k0 += BK) {
        // --- load A tile (128 rows x 16 k) as float4, store transposed ---
        #pragma unroll
        for (int it = 0; it < 2; it++) {
            int idx = tid + it * 256;          // 0..511 float4 slots
            int row = idx >> 2;                // 0..127
            int kk  = (idx & 3) * 4;           // 0,4,8,12
            int gr  = m0 + row;
            float4 v = make_float4(0.f, 0.f, 0.f, 0.f);
            if (gr < M) {
                v = *(const float4*)(A + (size_t)gr * K + k0 + kk);
                if (bias) {
                    v.x = fmaxf(v.x + bias[k0 + kk + 0], 0.f);
                    v.y = fmaxf(v.y + bias[k0 + kk + 1], 0.f);
                    v.z = fmaxf(v.z + bias[k0 + kk + 2], 0.f);
                    v.w = fmaxf(v.w + bias[k0 + kk + 3], 0.f);
                }
            }
            As[kk + 0][row] = v.x;
            As[kk + 1][row] = v.y;
            As[kk + 2][row] = v.z;
            As[kk + 3][row] = v.w;
        }
        // --- load B tile (16 k x 128 n) as float4 ---
        #pragma unroll
        for (int it = 0; it < 2; it++) {
            int idx  = tid + it * 256;         // 0..511 float4 slots
            int krow = idx >> 5;               // 0..15
            int n4   = (idx & 31) * 4;         // 0..124
            float4 v = *(const float4*)(B + (size_t)(k0 + krow) * BN + n4);
            *(float4*)&Bs[krow][n4] = v;
        }
        __syncthreads();

        // --- 8x8 micro-tile FMA ---
        #pragma unroll
        for (int k = 0; k < BK; k++) {
            float a[8], b[8];
            float4 a0 = *(const float4*)&As[k][ty * 8];
            float4 a1 = *(const float4*)&As[k][ty * 8 + 4];
            a[0]=a0.x; a[1]=a0.y; a[2]=a0.z; a[3]=a0.w;
            a[4]=a1.x; a[5]=a1.y; a[6]=a1.z; a[7]=a1.w;
            float4 b0 = *(const float4*)&Bs[k][tx * 8];
            float4 b1 = *(const float4*)&Bs[k][tx * 8 + 4];
            b[0]=b0.x; b[1]=b0.y; b[2]=b0.z; b[3]=b0.w;
            b[4]=b1.x; b[5]=b1.y; b[6]=b1.z; b[7]=b1.w;
            #pragma unroll
            for (int i = 0; i < 8; i++)
                #pragma unroll
                for (int j = 0; j < 8; j++)
                    acc[i][j] = fmaf(a[i], b[j], acc[i][j]);
        }
        __syncthreads();
    }

    // --- store ---
    #pragma unroll
    for (int i = 0; i < 8; i++) {
        int gr = m0 + ty * 8 + i;
        if (gr < M) {
            #pragma unroll
            for (int j = 0; j < 8; j += 4) {
                float4 v = make_float4(acc[i][j], acc[i][j+1], acc[i][j+2], acc[i][j+3]);
                *(float4*)(C + (size_t)gr * BN + tx * 8 + j) = v;
            }
        }
    }
}

// ---------------- edge scatter: agg[dst] += H[src] * w   (one warp per edge) ----------------
__global__ __launch_bounds__(256) void scatter_edges(
    const float* __restrict__ H, const int* __restrict__ src, const int* __restrict__ dst,
    const float* __restrict__ ew, float* __restrict__ agg, int E)
{
    int gt   = blockIdx.x * blockDim.x + threadIdx.x;
    int w    = gt >> 5;        // edge id
    int lane = gt & 31;        // 4-column group
    if (w >= E) return;

    int   s  = __ldg(&src[w]);
    int   d  = __ldg(&dst[w]);
    float wt = __ldg(&ew[w]);

    float4 v = *(const float4*)(H + (size_t)s * NHID + lane * 4);
    v.x *= wt; v.y *= wt; v.z *= wt; v.w *= wt;

    float* a = agg + (size_t)d * NHID + lane * 4;
    asm volatile("red.global.add.v4.f32 [%0], {%1, %2, %3, %4};"
                 :: "l"(a), "f"(v.x), "f"(v.y), "f"(v.z), "f"(v.w)
                 : "memory");
}

// ---------------- finalize: out = [agg[:, :64] + bmu ; agg[:, 64:] + blv] ----------------
__global__ void finalize(const float* __restrict__ agg,
                         const float* __restrict__ bmu, const float* __restrict__ blv,
                         float* __restrict__ out) {
    int i = blockIdx.x * blockDim.x + threadIdx.x;
    if (i >= N_NODES * LATENT) return;
    int n = i >> 6, j = i & 63;
    const float* row = agg + (size_t)n * NHID;
    out[i] = row[j] + bmu[j];
    out[(size_t)N_NODES * LATENT + i] = row[LATENT + j] + blv[j];
}

// ---------------- launch ----------------
extern "C" void kernel_launch(void* const* d_in, const int* in_sizes, int n_in,
                              void* d_out, int out_size) {
    const float* x   = (const float*)d_in[0];
    const int*   src = (const int*)  d_in[1];
    const int*   dst = (const int*)  d_in[2];
    const float* ew  = (const float*)d_in[3];
    const float* W1  = (const float*)d_in[4];
    const float* b1  = (const float*)d_in[5];
    const float* Wmu = (const float*)d_in[6];
    const float* bmu = (const float*)d_in[7];
    const float* Wlv = (const float*)d_in[8];
    const float* blv = (const float*)d_in[9];
    float* out = (float*)d_out;
    const int E = in_sizes[1];

    float *hpre, *agg, *hz, *wcat;
    cudaGetSymbolAddress((void**)&hpre, g_hpre);
    cudaGetSymbolAddress((void**)&agg,  g_agg);
    cudaGetSymbolAddress((void**)&hz,   g_hz);
    cudaGetSymbolAddress((void**)&wcat, g_wcat);

    const int n4 = N_NODES * NHID / 4;                 // 1.6M float4
    const int gemm_grid = (N_NODES + BM - 1) / BM;     // 391
    const int scat_grid = (E * 32 + 255) / 256;        // warp per edge

    // Layer 1: agg1 = segsum( (x@W1)[src] * w , dst )
    zero_kernel<<<(n4 + 255) / 256, 256>>>((float4*)agg, n4);
    gemm_bias_relu<<<gemm_grid, 256>>>(x, W1, hpre, N_NODES, NFEAT, nullptr);
    pack_wcat<<<64, 256>>>(Wmu, Wlv, wcat);
    scatter_edges<<<scat_grid, 256>>>(hpre, src, dst, ew, agg, E);

    // Layer 2: hz = relu(agg1 + b1) @ [Wmu|Wlv]   (relu+bias fused into A-read)
    gemm_bias_relu<<<gemm_grid, 256>>>(agg, wcat, hz, N_NODES, NHID, b1);

    // agg2 = segsum( hz[src] * w , dst )
    zero_kernel<<<(n4 + 255) / 256, 256>>>((float4*)agg, n4);
    scatter_edges<<<scat_grid, 256>>>(hz, src, dst, ew, agg, E);

    // out = (agg2[:, :64] + bmu, agg2[:, 64:] + blv)
    finalize<<<(N_NODES * LATENT + 255) / 256, 256>>>(agg, bmu, blv, out);
}

// round 4
// speedup vs baseline: 1.2331x; 1.2331x over previous
#include <cuda_runtime.h>
#include <cuda_bf16.h>
#include <cstdint>

#define N_NODES 50000
#define NFEAT   256
#define NHID    128
#define LATENT  64

// ---------------- scratch (no allocations allowed) ----------------
__device__ float g_hpre[(size_t)N_NODES * NHID];   // x@W1 (layer-1 messages)
__device__ float g_h   [(size_t)N_NODES * NHID];   // relu(agg1 + b1)
__device__ float g_hz  [(size_t)N_NODES * NHID];   // h@[Wmu|Wlv]
__device__ float g_wcat[NHID * NHID];              // [Wmu | Wlv] packed 128x128
__device__ int   g_cnt [N_NODES];                  // in-degree histogram
__device__ int   g_rowptr[N_NODES + 1];            // CSR row offsets (by dst)
__device__ int   g_woff[N_NODES];                  // working offsets for bucket fill
__device__ int2  g_ep  [800000];                   // (src, weight-bits) sorted by dst

// ---------------- small utility kernels ----------------
__global__ void zero_int(int* p, int n) {
    int i = blockIdx.x * blockDim.x + threadIdx.x;
    if (i < n) p[i] = 0;
}

__global__ void pack_wcat(const float* __restrict__ Wmu, const float* __restrict__ Wlv,
                          float* __restrict__ Wcat) {
    int i = blockIdx.x * blockDim.x + threadIdx.x;
    if (i >= NHID * NHID) return;
    int k = i >> 7, n = i & 127;
    Wcat[i] = (n < LATENT) ? Wmu[k * LATENT + n] : Wlv[k * LATENT + (n - LATENT)];
}

// ---------------- CSR build ----------------
__global__ void hist_kernel(const int* __restrict__ dst, int* __restrict__ cnt, int E) {
    int e = blockIdx.x * blockDim.x + threadIdx.x;
    if (e < E) atomicAdd(&cnt[dst[e]], 1);
}

__global__ void scan_kernel(const int* __restrict__ cnt, int* __restrict__ rowptr,
                            int* __restrict__ woff, int E) {
    __shared__ int sums[1024];
    const int tid = threadIdx.x;
    const int CH = (N_NODES + 1023) / 1024;
    const int base = tid * CH;
    int s = 0;
    for (int i = 0; i < CH; i++) {
        int n = base + i;
        if (n < N_NODES) s += cnt[n];
    }
    sums[tid] = s;
    __syncthreads();
    for (int d = 1; d < 1024; d <<= 1) {          // Hillis-Steele inclusive scan
        int add = (tid >= d) ? sums[tid - d] : 0;
        __syncthreads();
        sums[tid] += add;
        __syncthreads();
    }
    int off = sums[tid] - s;                       // exclusive offset
    for (int i = 0; i < CH; i++) {
        int n = base + i;
        if (n < N_NODES) {
            rowptr[n] = off;
            woff[n]   = off;
            off += cnt[n];
        }
    }
    if (tid == 0) rowptr[N_NODES] = E;
}

__global__ void fill_kernel(const int* __restrict__ src, const int* __restrict__ dst,
                            const float* __restrict__ ew, int* __restrict__ woff,
                            int2* __restrict__ ep, int E) {
    int e = blockIdx.x * blockDim.x + threadIdx.x;
    if (e < E) {
        int p = atomicAdd(&woff[dst[e]], 1);
        ep[p] = make_int2(src[e], __float_as_int(ew[e]));
    }
}

// ---------------- CSR gather: one warp per node ----------------
// MODE 0: out[node,:] = relu(acc + b0)                       (layer 1, 128 wide)
// MODE 1: out[:N*64]   = acc[:64]  + b0  (mu)
//         out[N*64:]   = acc[64:]  + b1v (logvar)            (layer 2, split)
template<int MODE>
__global__ __launch_bounds__(256) void gather_csr(
    const float* __restrict__ H, const int2* __restrict__ ep,
    const int* __restrict__ rowptr,
    const float* __restrict__ b0, const float* __restrict__ b1v,
    float* __restrict__ out)
{
    const int node = (blockIdx.x * blockDim.x + threadIdx.x) >> 5;
    const int lane = threadIdx.x & 31;
    if (node >= N_NODES) return;
    const int beg = __ldg(&rowptr[node]);
    const int end = __ldg(&rowptr[node + 1]);
    float4 acc = make_float4(0.f, 0.f, 0.f, 0.f);
    for (int j = beg; j < end; j++) {
        int2 p = __ldg(&ep[j]);                                   // warp-uniform broadcast
        float w = __int_as_float(p.y);
        float4 v = __ldg((const float4*)(H + (size_t)p.x * NHID) + lane);
        acc.x = fmaf(v.x, w, acc.x);
        acc.y = fmaf(v.y, w, acc.y);
        acc.z = fmaf(v.z, w, acc.z);
        acc.w = fmaf(v.w, w, acc.w);
    }
    if (MODE == 0) {
        float4 b = __ldg((const float4*)b0 + lane);
        acc.x = fmaxf(acc.x + b.x, 0.f);
        acc.y = fmaxf(acc.y + b.y, 0.f);
        acc.z = fmaxf(acc.z + b.z, 0.f);
        acc.w = fmaxf(acc.w + b.w, 0.f);
        *((float4*)(out + (size_t)node * NHID) + lane) = acc;
    } else {
        if (lane < 16) {
            float4 b = __ldg((const float4*)b0 + lane);
            acc.x += b.x; acc.y += b.y; acc.z += b.z; acc.w += b.w;
            *((float4*)(out + (size_t)node * LATENT) + lane) = acc;
        } else {
            float4 b = __ldg((const float4*)b1v + (lane - 16));
            acc.x += b.x; acc.y += b.y; acc.z += b.z; acc.w += b.w;
            *((float4*)(out + (size_t)N_NODES * LATENT + (size_t)node * LATENT) + (lane - 16)) = acc;
        }
    }
}

// ---------------- tf32 tensor-core GEMM with 3x-split compensation ----------------
// C[M,128] = A[M,K] @ B[K,128], fp32 in/out, error ~2^-22 (hi*hi + hi*lo + lo*hi)
__device__ __forceinline__ uint32_t f2tf32(float v) {
    uint32_t r;
    asm("cvt.rna.tf32.f32 %0, %1;" : "=r"(r) : "f"(v));
    return r;
}

#define MMA_TF32(c, a0, a1, a2, a3, b0, b1)                                   \
    asm volatile("mma.sync.aligned.m16n8k8.row.col.f32.tf32.tf32.f32 "        \
                 "{%0,%1,%2,%3}, {%4,%5,%6,%7}, {%8,%9}, {%0,%1,%2,%3};"      \
                 : "+f"((c)[0]), "+f"((c)[1]), "+f"((c)[2]), "+f"((c)[3])     \
                 : "r"(a0), "r"(a1), "r"(a2), "r"(a3), "r"(b0), "r"(b1))

#define APAD 136   // 128 + 8 : frag LDS addr = 8t+g -> conflict-free

__global__ __launch_bounds__(256) void gemm_tf32(
    const float* __restrict__ A, const float* __restrict__ B, float* __restrict__ C,
    int M, int K)
{
    __shared__ float Ah[16][APAD];
    __shared__ float Al[16][APAD];
    __shared__ float Bh[16][APAD];
    __shared__ float Bl[16][APAD];

    const int tid  = threadIdx.x;
    const int wid  = tid >> 5;
    const int lane = tid & 31;
    const int g    = lane >> 2;      // groupID
    const int t    = lane & 3;       // threadID_in_group
    const int wm   = (wid >> 1) * 32;  // warp row base (4 warps over M)
    const int wn   = (wid & 1) * 64;   // warp col base (2 warps over N)
    const int m0   = blockIdx.x * 128;

    float acc[2][8][4] = {};

    for (int k0 = 0; k0 < K; k0 += 16) {
        // --- A tile: 128 rows x 16 k, split + transposed store [k][m] ---
        #pragma unroll
        for (int it = 0; it < 2; it++) {
            int idx = tid + it * 256;          // 512 float4 slots
            int row = idx >> 2;
            int kk  = (idx & 3) * 4;
            int gr  = m0 + row;
            float4 v = make_float4(0.f, 0.f, 0.f, 0.f);
            if (gr < M) v = *(const float4*)(A + (size_t)gr * K + k0 + kk);
            float vv[4] = {v.x, v.y, v.z, v.w};
            #pragma unroll
            for (int c = 0; c < 4; c++) {
                float hi = __uint_as_float(f2tf32(vv[c]));
                float lo = __uint_as_float(f2tf32(vv[c] - hi));
                Ah[kk + c][row] = hi;
                Al[kk + c][row] = lo;
            }
        }
        // --- B tile: 16 k x 128 n, split, vectorized store ---
        #pragma unroll
        for (int it = 0; it < 2; it++) {
            int idx  = tid + it * 256;
            int krow = idx >> 5;
            int n4   = (idx & 31) * 4;
            float4 v = *(const float4*)(B + (size_t)(k0 + krow) * 128 + n4);
            float vv[4] = {v.x, v.y, v.z, v.w};
            float4 hi4, lo4;
            float* hp = &hi4.x; float* lp = &lo4.x;
            #pragma unroll
            for (int c = 0; c < 4; c++) {
                float hi = __uint_as_float(f2tf32(vv[c]));
                hp[c] = hi;
                lp[c] = __uint_as_float(f2tf32(vv[c] - hi));
            }
            *(float4*)&Bh[krow][n4] = hi4;
            *(float4*)&Bl[krow][n4] = lo4;
        }
        __syncthreads();

        #pragma unroll
        for (int ks = 0; ks < 16; ks += 8) {
            uint32_t ah[2][4], al[2][4];
            #pragma unroll
            for (int mt = 0; mt < 2; mt++) {
                int mr = wm + mt * 16 + g;
                ah[mt][0] = __float_as_uint(Ah[ks + t][mr]);
                ah[mt][1] = __float_as_uint(Ah[ks + t][mr + 8]);
                ah[mt][2] = __float_as_uint(Ah[ks + t + 4][mr]);
                ah[mt][3] = __float_as_uint(Ah[ks + t + 4][mr + 8]);
                al[mt][0] = __float_as_uint(Al[ks + t][mr]);
                al[mt][1] = __float_as_uint(Al[ks + t][mr + 8]);
                al[mt][2] = __float_as_uint(Al[ks + t + 4][mr]);
                al[mt][3] = __float_as_uint(Al[ks + t + 4][mr + 8]);
            }
            #pragma unroll
            for (int nt = 0; nt < 8; nt++) {
                int nc = wn + nt * 8 + g;
                uint32_t bh0 = __float_as_uint(Bh[ks + t][nc]);
                uint32_t bh1 = __float_as_uint(Bh[ks + t + 4][nc]);
                uint32_t bl0 = __float_as_uint(Bl[ks + t][nc]);
                uint32_t bl1 = __float_as_uint(Bl[ks + t + 4][nc]);
                #pragma unroll
                for (int mt = 0; mt < 2; mt++) {
                    MMA_TF32(acc[mt][nt], ah[mt][0], ah[mt][1], ah[mt][2], ah[mt][3], bh0, bh1);
                    MMA_TF32(acc[mt][nt], ah[mt][0], ah[mt][1], ah[mt][2], ah[mt][3], bl0, bl1);
                    MMA_TF32(acc[mt][nt], al[mt][0], al[mt][1], al[mt][2], al[mt][3], bh0, bh1);
                }
            }
        }
        __syncthreads();
    }

    // --- store C: c0/c1 -> (row g, cols 2t,2t+1); c2/c3 -> row g+8 ---
    #pragma unroll
    for (int mt = 0; mt < 2; mt++) {
        #pragma unroll
        for (int nt = 0; nt < 8; nt++) {
            int row = m0 + wm + mt * 16 + g;
            int col = wn + nt * 8 + 2 * t;
            if (row < M)
                *(float2*)(C + (size_t)row * 128 + col) =
                    make_float2(acc[mt][nt][0], acc[mt][nt][1]);
            if (row + 8 < M)
                *(float2*)(C + (size_t)(row + 8) * 128 + col) =
                    make_float2(acc[mt][nt][2], acc[mt][nt][3]);
        }
    }
}

// ---------------- launch ----------------
extern "C" void kernel_launch(void* const* d_in, const int* in_sizes, int n_in,
                              void* d_out, int out_size) {
    const float* x   = (const float*)d_in[0];
    const int*   src = (const int*)  d_in[1];
    const int*   dst = (const int*)  d_in[2];
    const float* ew  = (const float*)d_in[3];
    const float* W1  = (const float*)d_in[4];
    const float* b1  = (const float*)d_in[5];
    const float* Wmu = (const float*)d_in[6];
    const float* bmu = (const float*)d_in[7];
    const float* Wlv = (const float*)d_in[8];
    const float* blv = (const float*)d_in[9];
    float* out = (float*)d_out;
    const int E = in_sizes[1];

    float *hpre, *h, *hz, *wcat;
    int *cnt, *rowptr, *woff;
    int2 *ep;
    cudaGetSymbolAddress((void**)&hpre,   g_hpre);
    cudaGetSymbolAddress((void**)&h,      g_h);
    cudaGetSymbolAddress((void**)&hz,     g_hz);
    cudaGetSymbolAddress((void**)&wcat,   g_wcat);
    cudaGetSymbolAddress((void**)&cnt,    g_cnt);
    cudaGetSymbolAddress((void**)&rowptr, g_rowptr);
    cudaGetSymbolAddress((void**)&woff,   g_woff);
    cudaGetSymbolAddress((void**)&ep,     g_ep);

    const int gemm_grid   = (N_NODES + 127) / 128;          // 391
    const int edge_grid   = (E + 255) / 256;
    const int gather_grid = (N_NODES * 32 + 255) / 256;     // warp per node

    // CSR build (by dst)
    zero_int<<<(N_NODES + 255) / 256, 256>>>(cnt, N_NODES);
    hist_kernel<<<edge_grid, 256>>>(dst, cnt, E);
    scan_kernel<<<1, 1024>>>(cnt, rowptr, woff, E);
    fill_kernel<<<edge_grid, 256>>>(src, dst, ew, woff, ep, E);

    // Layer 1: hpre = x@W1 ; h = relu(segsum(hpre[src]*w, dst) + b1)
    gemm_tf32<<<gemm_grid, 256>>>(x, W1, hpre, N_NODES, NFEAT);
    pack_wcat<<<64, 256>>>(Wmu, Wlv, wcat);
    gather_csr<0><<<gather_grid, 256>>>(hpre, ep, rowptr, b1, nullptr, h);

    // Layer 2: hz = h@[Wmu|Wlv] ; out = segsum(hz[src]*w, dst) + [bmu;blv] split
    gemm_tf32<<<gemm_grid, 256>>>(h, wcat, hz, N_NODES, NHID);
    gather_csr<1><<<gather_grid, 256>>>(hz, ep, rowptr, bmu, blv, out);
}

// round 7
// speedup vs baseline: 1.7151x; 1.3909x over previous
#include <cuda_runtime.h>
#include <cuda_bf16.h>
#include <cstdint>

#define N_NODES 50000
#define NFEAT   256
#define NHID    128
#define LATENT  64
#define MAX_E   800000

// ---------------- scratch (no allocations allowed) ----------------
__device__ float g_hpre[(size_t)N_NODES * NHID];   // x@W1 (layer-1 messages)
__device__ float g_h   [(size_t)N_NODES * NHID];   // relu(agg1 + b1)
__device__ float g_hz  [(size_t)N_NODES * NHID];   // h@[Wmu|Wlv]
__device__ float g_wcat[NHID * NHID];              // [Wmu | Wlv] packed 128x128
__device__ int   g_cnt [53248];                    // in-degree histogram (padded for int4 scan)
__device__ int   g_rowptr[N_NODES + 1];            // CSR row offsets (by dst)
__device__ int   g_rank[MAX_E];                    // within-bucket rank per edge
__device__ int2  g_ep  [MAX_E];                    // (src, weight-bits) sorted by dst

// ---------------- small utility kernels ----------------
__global__ void zero_int(int* p, int n) {
    int i = blockIdx.x * blockDim.x + threadIdx.x;
    if (i < n) p[i] = 0;
}

__global__ void pack_wcat(const float* __restrict__ Wmu, const float* __restrict__ Wlv,
                          float* __restrict__ Wcat) {
    int i = blockIdx.x * blockDim.x + threadIdx.x;
    if (i >= NHID * NHID) return;
    int k = i >> 7, n = i & 127;
    Wcat[i] = (n < LATENT) ? Wmu[k * LATENT + n] : Wlv[k * LATENT + (n - LATENT)];
}

// ---------------- CSR build ----------------
__global__ void hist_kernel(const int* __restrict__ dst, int* __restrict__ cnt,
                            int* __restrict__ rank, int E) {
    int e = blockIdx.x * blockDim.x + threadIdx.x;
    if (e < E) rank[e] = atomicAdd(&cnt[dst[e]], 1);
}

// single-block scan, int4-vectorized two-pass read
__global__ void scan_kernel(const int* __restrict__ cnt, int* __restrict__ rowptr, int E) {
    __shared__ int sums[1024];
    const int tid = threadIdx.x;
    const int4* c4 = (const int4*)cnt;
    const int b4 = tid * 13;                      // 13 int4 = 52 nodes per thread

    int s = 0;
    #pragma unroll
    for (int i = 0; i < 13; i++) {
        int4 v = c4[b4 + i];
        s += v.x + v.y + v.z + v.w;
    }
    sums[tid] = s;
    __syncthreads();
    #pragma unroll
    for (int d = 1; d < 1024; d <<= 1) {          // Hillis-Steele inclusive
        int add = (tid >= d) ? sums[tid - d] : 0;
        __syncthreads();
        sums[tid] += add;
        __syncthreads();
    }
    int off = sums[tid] - s;                       // exclusive offset
    #pragma unroll
    for (int i = 0; i < 13; i++) {
        int4 v = c4[b4 + i];
        int n = (b4 + i) * 4;
        if (n + 0 < N_NODES) { rowptr[n + 0] = off; off += v.x; }
        if (n + 1 < N_NODES) { rowptr[n + 1] = off; off += v.y; }
        if (n + 2 < N_NODES) { rowptr[n + 2] = off; off += v.z; }
        if (n + 3 < N_NODES) { rowptr[n + 3] = off; off += v.w; }
    }
    if (tid == 0) rowptr[N_NODES] = E;
}

// atomic-free bucket fill using precomputed ranks
__global__ void fill_kernel(const int* __restrict__ src, const int* __restrict__ dst,
                            const float* __restrict__ ew, const int* __restrict__ rank,
                            const int* __restrict__ rowptr, int2* __restrict__ ep, int E) {
    int e = blockIdx.x * blockDim.x + threadIdx.x;
    if (e < E) {
        int p = __ldg(&rowptr[dst[e]]) + rank[e];
        ep[p] = make_int2(src[e], __float_as_int(ew[e]));
    }
}

// ---------------- CSR gather: one warp per node, unroll-4 pipeline ----------------
// MODE 0: out[node,:] = relu(acc + b0)                       (layer 1, 128 wide)
// MODE 1: out[:N*64] = acc[:64]+b0 (mu); out[N*64:] = acc[64:]+b1v (logvar)
template<int MODE>
__global__ __launch_bounds__(256) void gather_csr(
    const float* __restrict__ H, const int2* __restrict__ ep,
    const int* __restrict__ rowptr,
    const float* __restrict__ b0, const float* __restrict__ b1v,
    float* __restrict__ out)
{
    const int node = (blockIdx.x * blockDim.x + threadIdx.x) >> 5;
    const int lane = threadIdx.x & 31;
    if (node >= N_NODES) return;
    const int beg = __ldg(&rowptr[node]);
    const int end = __ldg(&rowptr[node + 1]);
    float4 acc = make_float4(0.f, 0.f, 0.f, 0.f);

    int j = beg;
    for (; j + 4 <= end; j += 4) {
        int2 e0 = __ldg(&ep[j]);
        int2 e1 = __ldg(&ep[j + 1]);
        int2 e2 = __ldg(&ep[j + 2]);
        int2 e3 = __ldg(&ep[j + 3]);
        float4 v0 = __ldg((const float4*)(H + (size_t)e0.x * NHID) + lane);
        float4 v1 = __ldg((const float4*)(H + (size_t)e1.x * NHID) + lane);
        float4 v2 = __ldg((const float4*)(H + (size_t)e2.x * NHID) + lane);
        float4 v3 = __ldg((const float4*)(H + (size_t)e3.x * NHID) + lane);
        float w0 = __int_as_float(e0.y), w1 = __int_as_float(e1.y);
        float w2 = __int_as_float(e2.y), w3 = __int_as_float(e3.y);
        acc.x = fmaf(v0.x, w0, acc.x); acc.y = fmaf(v0.y, w0, acc.y);
        acc.z = fmaf(v0.z, w0, acc.z); acc.w = fmaf(v0.w, w0, acc.w);
        acc.x = fmaf(v1.x, w1, acc.x); acc.y = fmaf(v1.y, w1, acc.y);
        acc.z = fmaf(v1.z, w1, acc.z); acc.w = fmaf(v1.w, w1, acc.w);
        acc.x = fmaf(v2.x, w2, acc.x); acc.y = fmaf(v2.y, w2, acc.y);
        acc.z = fmaf(v2.z, w2, acc.z); acc.w = fmaf(v2.w, w2, acc.w);
        acc.x = fmaf(v3.x, w3, acc.x); acc.y = fmaf(v3.y, w3, acc.y);
        acc.z = fmaf(v3.z, w3, acc.z); acc.w = fmaf(v3.w, w3, acc.w);
    }
    for (; j < end; j++) {
        int2 p = __ldg(&ep[j]);
        float w = __int_as_float(p.y);
        float4 v = __ldg((const float4*)(H + (size_t)p.x * NHID) + lane);
        acc.x = fmaf(v.x, w, acc.x); acc.y = fmaf(v.y, w, acc.y);
        acc.z = fmaf(v.z, w, acc.z); acc.w = fmaf(v.w, w, acc.w);
    }

    if (MODE == 0) {
        float4 b = __ldg((const float4*)b0 + lane);
        acc.x = fmaxf(acc.x + b.x, 0.f);
        acc.y = fmaxf(acc.y + b.y, 0.f);
        acc.z = fmaxf(acc.z + b.z, 0.f);
        acc.w = fmaxf(acc.w + b.w, 0.f);
        *((float4*)(out + (size_t)node * NHID) + lane) = acc;
    } else {
        if (lane < 16) {
            float4 b = __ldg((const float4*)b0 + lane);
            acc.x += b.x; acc.y += b.y; acc.z += b.z; acc.w += b.w;
            *((float4*)(out + (size_t)node * LATENT) + lane) = acc;
        } else {
            float4 b = __ldg((const float4*)b1v + (lane - 16));
            acc.x += b.x; acc.y += b.y; acc.z += b.z; acc.w += b.w;
            *((float4*)(out + (size_t)N_NODES * LATENT + (size_t)node * LATENT) + (lane - 16)) = acc;
        }
    }
}

// ---------------- tf32 tensor-core GEMM, cp.async double-buffered ----------------
// C[M,128] = A[M,K] @ B[K,128]; raw fp32 tiles in smem, tf32 hi/lo split at frag load.
__device__ __forceinline__ uint32_t f2tf32(float v) {
    uint32_t r;
    asm("cvt.rna.tf32.f32 %0, %1;" : "=r"(r) : "f"(v));
    return r;
}

__device__ __forceinline__ void cpasync16(void* smem_dst, const void* gsrc) {
    uint32_t d = (uint32_t)__cvta_generic_to_shared(smem_dst);
    asm volatile("cp.async.ca.shared.global [%0], [%1], 16;" :: "r"(d), "l"(gsrc));
}

#define MMA_TF32(c, a0, a1, a2, a3, b0, b1)                                   \
    asm volatile("mma.sync.aligned.m16n8k8.row.col.f32.tf32.tf32.f32 "        \
                 "{%0,%1,%2,%3}, {%4,%5,%6,%7}, {%8,%9}, {%0,%1,%2,%3};"      \
                 : "+f"((c)[0]), "+f"((c)[1]), "+f"((c)[2]), "+f"((c)[3])     \
                 : "r"(a0), "r"(a1), "r"(a2), "r"(a3), "r"(b0), "r"(b1))

#define PADA 20    // 128+... row stride 20 floats -> 20g mod 32 spaced >=4, +t(0..3) conflict-free
#define PADB 136   // 8t+g -> conflict-free

__global__ __launch_bounds__(256) void gemm_tf32(
    const float* __restrict__ A, const float* __restrict__ B, float* __restrict__ C,
    int M, int K)
{
    __shared__ __align__(16) float As[2][128][PADA];   // raw A, [row][k]
    __shared__ __align__(16) float Bs[2][16][PADB];    // raw B, [k][n]

    const int tid  = threadIdx.x;
    const int wid  = tid >> 5;
    const int lane = tid & 31;
    const int g    = lane >> 2;
    const int t    = lane & 3;
    const int wm   = (wid >> 1) * 32;
    const int wn   = (wid & 1) * 64;
    const int m0   = blockIdx.x * 128;

    float acc[2][8][4] = {};

    auto load_tiles = [&](int s, int k0) {
        #pragma unroll
        for (int it = 0; it < 2; it++) {
            int idx = tid + it * 256;          // 512 float4 slots
            int row = idx >> 2;
            int kk  = (idx & 3) << 2;
            int gr  = m0 + row;
            if (gr >= M) gr = M - 1;           // clamp: junk rows never stored
            cpasync16(&As[s][row][kk], A + (size_t)gr * K + k0 + kk);
        }
        #pragma unroll
        for (int it = 0; it < 2; it++) {
            int idx  = tid + it * 256;
            int krow = idx >> 5;
            int n4   = (idx & 31) << 2;
            cpasync16(&Bs[s][krow][n4], B + (size_t)(k0 + krow) * 128 + n4);
        }
    };

    const int KT = K >> 4;
    load_tiles(0, 0);
    asm volatile("cp.async.commit_group;");

    for (int kt = 0; kt < KT; kt++) {
        const int p = kt & 1;
        if (kt + 1 < KT) {
            load_tiles(p ^ 1, (kt + 1) << 4);
            asm volatile("cp.async.commit_group;");
            asm volatile("cp.async.wait_group 1;");
        } else {
            asm volatile("cp.async.wait_group 0;");
        }
        __syncthreads();

        #pragma unroll
        for (int ks = 0; ks < 16; ks += 8) {
            uint32_t ah[2][4], al[2][4];
            #pragma unroll
            for (int mt = 0; mt < 2; mt++) {
                int mr = wm + mt * 16 + g;
                float ar[4];
                ar[0] = As[p][mr][ks + t];
                ar[1] = As[p][mr + 8][ks + t];
                ar[2] = As[p][mr][ks + t + 4];
                ar[3] = As[p][mr + 8][ks + t + 4];
                #pragma unroll
                for (int q = 0; q < 4; q++) {
                    ah[mt][q] = f2tf32(ar[q]);
                    al[mt][q] = f2tf32(ar[q] - __uint_as_float(ah[mt][q]));
                }
            }
            #pragma unroll
            for (int nt = 0; nt < 8; nt++) {
                int nc = wn + nt * 8 + g;
                float br0 = Bs[p][ks + t][nc];
                float br1 = Bs[p][ks + t + 4][nc];
                uint32_t bh0 = f2tf32(br0);
                uint32_t bl0 = f2tf32(br0 - __uint_as_float(bh0));
                uint32_t bh1 = f2tf32(br1);
                uint32_t bl1 = f2tf32(br1 - __uint_as_float(bh1));
                #pragma unroll
                for (int mt = 0; mt < 2; mt++) {
                    MMA_TF32(acc[mt][nt], ah[mt][0], ah[mt][1], ah[mt][2], ah[mt][3], bh0, bh1);
                    MMA_TF32(acc[mt][nt], ah[mt][0], ah[mt][1], ah[mt][2], ah[mt][3], bl0, bl1);
                    MMA_TF32(acc[mt][nt], al[mt][0], al[mt][1], al[mt][2], al[mt][3], bh0, bh1);
                }
            }
        }
        __syncthreads();
    }

    #pragma unroll
    for (int mt = 0; mt < 2; mt++) {
        #pragma unroll
        for (int nt = 0; nt < 8; nt++) {
            int row = m0 + wm + mt * 16 + g;
            int col = wn + nt * 8 + 2 * t;
            if (row < M)
                *(float2*)(C + (size_t)row * 128 + col) =
                    make_float2(acc[mt][nt][0], acc[mt][nt][1]);
            if (row + 8 < M)
                *(float2*)(C + (size_t)(row + 8) * 128 + col) =
                    make_float2(acc[mt][nt][2], acc[mt][nt][3]);
        }
    }
}

// ---------------- launch ----------------
extern "C" void kernel_launch(void* const* d_in, const int* in_sizes, int n_in,
                              void* d_out, int out_size) {
    const float* x   = (const float*)d_in[0];
    const int*   src = (const int*)  d_in[1];
    const int*   dst = (const int*)  d_in[2];
    const float* ew  = (const float*)d_in[3];
    const float* W1  = (const float*)d_in[4];
    const float* b1  = (const float*)d_in[5];
    const float* Wmu = (const float*)d_in[6];
    const float* bmu = (const float*)d_in[7];
    const float* Wlv = (const float*)d_in[8];
    const float* blv = (const float*)d_in[9];
    float* out = (float*)d_out;
    const int E = in_sizes[1];

    float *hpre, *h, *hz, *wcat;
    int *cnt, *rowptr, *rank;
    int2 *ep;
    cudaGetSymbolAddress((void**)&hpre,   g_hpre);
    cudaGetSymbolAddress((void**)&h,      g_h);
    cudaGetSymbolAddress((void**)&hz,     g_hz);
    cudaGetSymbolAddress((void**)&wcat,   g_wcat);
    cudaGetSymbolAddress((void**)&cnt,    g_cnt);
    cudaGetSymbolAddress((void**)&rowptr, g_rowptr);
    cudaGetSymbolAddress((void**)&rank,   g_rank);
    cudaGetSymbolAddress((void**)&ep,     g_ep);

    const int gemm_grid   = (N_NODES + 127) / 128;          // 391
    const int edge_grid   = (E + 255) / 256;
    const int gather_grid = (N_NODES * 32 + 255) / 256;     // warp per node

    // CSR build (by dst): hist w/ rank capture -> vector scan -> atomic-free fill
    zero_int<<<(N_NODES + 255) / 256, 256>>>(cnt, N_NODES);
    hist_kernel<<<edge_grid, 256>>>(dst, cnt, rank, E);
    scan_kernel<<<1, 1024>>>(cnt, rowptr, E);
    fill_kernel<<<edge_grid, 256>>>(src, dst, ew, rank, rowptr, ep, E);

    // Layer 1: hpre = x@W1 ; h = relu(segsum(hpre[src]*w, dst) + b1)
    gemm_tf32<<<gemm_grid, 256>>>(x, W1, hpre, N_NODES, NFEAT);
    pack_wcat<<<64, 256>>>(Wmu, Wlv, wcat);
    gather_csr<0><<<gather_grid, 256>>>(hpre, ep, rowptr, b1, nullptr, h);

    // Layer 2: hz = h@[Wmu|Wlv] ; out = segsum(hz[src]*w, dst) + [bmu;blv] split
    gemm_tf32<<<gemm_grid, 256>>>(h, wcat, hz, N_NODES, NHID);
    gather_csr<1><<<gather_grid, 256>>>(hz, ep, rowptr, bmu, blv, out);
}

// round 8
// speedup vs baseline: 1.8984x; 1.1069x over previous
#include <cuda_runtime.h>
#include <cuda_bf16.h>
#include <cstdint>

#define N_NODES 50000
#define NFEAT   256
#define NHID    128
#define LATENT  64
#define MAX_E   800000

// ---------------- scratch (no allocations allowed) ----------------
__device__ float g_hpre[(size_t)N_NODES * NHID];   // x@W1 (layer-1 messages)
__device__ float g_h   [(size_t)N_NODES * NHID];   // relu(agg1 + b1)
__device__ float g_hz  [(size_t)N_NODES * NHID];   // h@[Wmu|Wlv]
__device__ float g_wcat[NHID * NHID];              // [Wmu | Wlv] packed 128x128
__device__ int   g_cnt [53248];                    // in-degree histogram (padded for int4 scan)
__device__ int   g_rowptr[N_NODES + 1];            // CSR row offsets (by dst)
__device__ int   g_rank[MAX_E];                    // within-bucket rank per edge
__device__ int2  g_ep  [MAX_E];                    // (src, weight-bits) sorted by dst

// ---------------- small utility kernels ----------------
__global__ void zero_int(int* p, int n) {
    int i = blockIdx.x * blockDim.x + threadIdx.x;
    if (i < n) p[i] = 0;
}

__global__ void pack_wcat(const float* __restrict__ Wmu, const float* __restrict__ Wlv,
                          float* __restrict__ Wcat) {
    int i = blockIdx.x * blockDim.x + threadIdx.x;
    if (i >= NHID * NHID) return;
    int k = i >> 7, n = i & 127;
    Wcat[i] = (n < LATENT) ? Wmu[k * LATENT + n] : Wlv[k * LATENT + (n - LATENT)];
}

// ---------------- CSR build ----------------
__global__ void hist_kernel(const int* __restrict__ dst, int* __restrict__ cnt,
                            int* __restrict__ rank, int E) {
    int e = blockIdx.x * blockDim.x + threadIdx.x;
    if (e < E) rank[e] = atomicAdd(&cnt[dst[e]], 1);
}

// single-block scan, int4-vectorized two-pass read
__global__ void scan_kernel(const int* __restrict__ cnt, int* __restrict__ rowptr, int E) {
    __shared__ int sums[1024];
    const int tid = threadIdx.x;
    const int4* c4 = (const int4*)cnt;
    const int b4 = tid * 13;                      // 13 int4 = 52 nodes per thread

    int s = 0;
    #pragma unroll
    for (int i = 0; i < 13; i++) {
        int4 v = c4[b4 + i];
        s += v.x + v.y + v.z + v.w;
    }
    sums[tid] = s;
    __syncthreads();
    #pragma unroll
    for (int d = 1; d < 1024; d <<= 1) {          // Hillis-Steele inclusive
        int add = (tid >= d) ? sums[tid - d] : 0;
        __syncthreads();
        sums[tid] += add;
        __syncthreads();
    }
    int off = sums[tid] - s;                       // exclusive offset
    #pragma unroll
    for (int i = 0; i < 13; i++) {
        int4 v = c4[b4 + i];
        int n = (b4 + i) * 4;
        if (n + 0 < N_NODES) { rowptr[n + 0] = off; off += v.x; }
        if (n + 1 < N_NODES) { rowptr[n + 1] = off; off += v.y; }
        if (n + 2 < N_NODES) { rowptr[n + 2] = off; off += v.z; }
        if (n + 3 < N_NODES) { rowptr[n + 3] = off; off += v.w; }
    }
    if (tid == 0) rowptr[N_NODES] = E;
}

// atomic-free bucket fill using precomputed ranks
__global__ void fill_kernel(const int* __restrict__ src, const int* __restrict__ dst,
                            const float* __restrict__ ew, const int* __restrict__ rank,
                            const int* __restrict__ rowptr, int2* __restrict__ ep, int E) {
    int e = blockIdx.x * blockDim.x + threadIdx.x;
    if (e < E) {
        int p = __ldg(&rowptr[dst[e]]) + rank[e];
        ep[p] = make_int2(src[e], __float_as_int(ew[e]));
    }
}

// ---------------- CSR gather: one warp per node, unroll-4 pipeline ----------------
// MODE 0: out[node,:] = relu(acc + b0)                       (layer 1, 128 wide)
// MODE 1: out[:N*64] = acc[:64]+b0 (mu); out[N*64:] = acc[64:]+b1v (logvar)
template<int MODE>
__global__ __launch_bounds__(256) void gather_csr(
    const float* __restrict__ H, const int2* __restrict__ ep,
    const int* __restrict__ rowptr,
    const float* __restrict__ b0, const float* __restrict__ b1v,
    float* __restrict__ out)
{
    const int node = (blockIdx.x * blockDim.x + threadIdx.x) >> 5;
    const int lane = threadIdx.x & 31;
    if (node >= N_NODES) return;
    const int beg = __ldg(&rowptr[node]);
    const int end = __ldg(&rowptr[node + 1]);
    float4 acc = make_float4(0.f, 0.f, 0.f, 0.f);

    int j = beg;
    for (; j + 4 <= end; j += 4) {
        int2 e0 = __ldg(&ep[j]);
        int2 e1 = __ldg(&ep[j + 1]);
        int2 e2 = __ldg(&ep[j + 2]);
        int2 e3 = __ldg(&ep[j + 3]);
        float4 v0 = __ldg((const float4*)(H + (size_t)e0.x * NHID) + lane);
        float4 v1 = __ldg((const float4*)(H + (size_t)e1.x * NHID) + lane);
        float4 v2 = __ldg((const float4*)(H + (size_t)e2.x * NHID) + lane);
        float4 v3 = __ldg((const float4*)(H + (size_t)e3.x * NHID) + lane);
        float w0 = __int_as_float(e0.y), w1 = __int_as_float(e1.y);
        float w2 = __int_as_float(e2.y), w3 = __int_as_float(e3.y);
        acc.x = fmaf(v0.x, w0, acc.x); acc.y = fmaf(v0.y, w0, acc.y);
        acc.z = fmaf(v0.z, w0, acc.z); acc.w = fmaf(v0.w, w0, acc.w);
        acc.x = fmaf(v1.x, w1, acc.x); acc.y = fmaf(v1.y, w1, acc.y);
        acc.z = fmaf(v1.z, w1, acc.z); acc.w = fmaf(v1.w, w1, acc.w);
        acc.x = fmaf(v2.x, w2, acc.x); acc.y = fmaf(v2.y, w2, acc.y);
        acc.z = fmaf(v2.z, w2, acc.z); acc.w = fmaf(v2.w, w2, acc.w);
        acc.x = fmaf(v3.x, w3, acc.x); acc.y = fmaf(v3.y, w3, acc.y);
        acc.z = fmaf(v3.z, w3, acc.z); acc.w = fmaf(v3.w, w3, acc.w);
    }
    for (; j < end; j++) {
        int2 p = __ldg(&ep[j]);
        float w = __int_as_float(p.y);
        float4 v = __ldg((const float4*)(H + (size_t)p.x * NHID) + lane);
        acc.x = fmaf(v.x, w, acc.x); acc.y = fmaf(v.y, w, acc.y);
        acc.z = fmaf(v.z, w, acc.z); acc.w = fmaf(v.w, w, acc.w);
    }

    if (MODE == 0) {
        float4 b = __ldg((const float4*)b0 + lane);
        acc.x = fmaxf(acc.x + b.x, 0.f);
        acc.y = fmaxf(acc.y + b.y, 0.f);
        acc.z = fmaxf(acc.z + b.z, 0.f);
        acc.w = fmaxf(acc.w + b.w, 0.f);
        *((float4*)(out + (size_t)node * NHID) + lane) = acc;
    } else {
        if (lane < 16) {
            float4 b = __ldg((const float4*)b0 + lane);
            acc.x += b.x; acc.y += b.y; acc.z += b.z; acc.w += b.w;
            *((float4*)(out + (size_t)node * LATENT) + lane) = acc;
        } else {
            float4 b = __ldg((const float4*)b1v + (lane - 16));
            acc.x += b.x; acc.y += b.y; acc.z += b.z; acc.w += b.w;
            *((float4*)(out + (size_t)N_NODES * LATENT + (size_t)node * LATENT) + (lane - 16)) = acc;
        }
    }
}

// ---------------- tf32 tensor-core GEMM, cp.async double-buffered ----------------
// C[M,128] = A[M,K] @ B[K,128]; raw fp32 tiles in smem, tf32 hi/lo split at frag load.
__device__ __forceinline__ uint32_t f2tf32(float v) {
    uint32_t r;
    asm("cvt.rna.tf32.f32 %0, %1;" : "=r"(r) : "f"(v));
    return r;
}

__device__ __forceinline__ void cpasync16(void* smem_dst, const void* gsrc) {
    uint32_t d = (uint32_t)__cvta_generic_to_shared(smem_dst);
    asm volatile("cp.async.ca.shared.global [%0], [%1], 16;" :: "r"(d), "l"(gsrc));
}

#define MMA_TF32(c, a0, a1, a2, a3, b0, b1)                                   \
    asm volatile("mma.sync.aligned.m16n8k8.row.col.f32.tf32.tf32.f32 "        \
                 "{%0,%1,%2,%3}, {%4,%5,%6,%7}, {%8,%9}, {%0,%1,%2,%3};"      \
                 : "+f"((c)[0]), "+f"((c)[1]), "+f"((c)[2]), "+f"((c)[3])     \
                 : "r"(a0), "r"(a1), "r"(a2), "r"(a3), "r"(b0), "r"(b1))

#define PADA 20    // row stride 20 floats -> frag LDS conflict-free
#define PADB 136   // 8t+g -> conflict-free

__global__ __launch_bounds__(256) void gemm_tf32(
    const float* __restrict__ A, const float* __restrict__ B, float* __restrict__ C,
    int M, int K)
{
    __shared__ __align__(16) float As[2][128][PADA];   // raw A, [row][k]
    __shared__ __align__(16) float Bs[2][16][PADB];    // raw B, [k][n]

    const int tid  = threadIdx.x;
    const int wid  = tid >> 5;
    const int lane = tid & 31;
    const int g    = lane >> 2;
    const int t    = lane & 3;
    const int wm   = (wid >> 1) * 32;
    const int wn   = (wid & 1) * 64;
    const int m0   = blockIdx.x * 128;

    float acc[2][8][4] = {};

    auto load_tiles = [&](int s, int k0) {
        #pragma unroll
        for (int it = 0; it < 2; it++) {
            int idx = tid + it * 256;          // 512 float4 slots
            int row = idx >> 2;
            int kk  = (idx & 3) << 2;
            int gr  = m0 + row;
            if (gr >= M) gr = M - 1;           // clamp: junk rows never stored
            cpasync16(&As[s][row][kk], A + (size_t)gr * K + k0 + kk);
        }
        #pragma unroll
        for (int it = 0; it < 2; it++) {
            int idx  = tid + it * 256;
            int krow = idx >> 5;
            int n4   = (idx & 31) << 2;
            cpasync16(&Bs[s][krow][n4], B + (size_t)(k0 + krow) * 128 + n4);
        }
    };

    const int KT = K >> 4;
    load_tiles(0, 0);
    asm volatile("cp.async.commit_group;");

    for (int kt = 0; kt < KT; kt++) {
        const int p = kt & 1;
        if (kt + 1 < KT) {
            load_tiles(p ^ 1, (kt + 1) << 4);
            asm volatile("cp.async.commit_group;");
            asm volatile("cp.async.wait_group 1;");
        } else {
            asm volatile("cp.async.wait_group 0;");
        }
        __syncthreads();

        #pragma unroll
        for (int ks = 0; ks < 16; ks += 8) {
            uint32_t ah[2][4], al[2][4];
            #pragma unroll
            for (int mt = 0; mt < 2; mt++) {
                int mr = wm + mt * 16 + g;
                float ar[4];
                ar[0] = As[p][mr][ks + t];
                ar[1] = As[p][mr + 8][ks + t];
                ar[2] = As[p][mr][ks + t + 4];
                ar[3] = As[p][mr + 8][ks + t + 4];
                #pragma unroll
                for (int q = 0; q < 4; q++) {
                    ah[mt][q] = f2tf32(ar[q]);
                    al[mt][q] = f2tf32(ar[q] - __uint_as_float(ah[mt][q]));
                }
            }
            #pragma unroll
            for (int nt = 0; nt < 8; nt++) {
                int nc = wn + nt * 8 + g;
                float br0 = Bs[p][ks + t][nc];
                float br1 = Bs[p][ks + t + 4][nc];
                uint32_t bh0 = f2tf32(br0);
                uint32_t bl0 = f2tf32(br0 - __uint_as_float(bh0));
                uint32_t bh1 = f2tf32(br1);
                uint32_t bl1 = f2tf32(br1 - __uint_as_float(bh1));
                #pragma unroll
                for (int mt = 0; mt < 2; mt++) {
                    MMA_TF32(acc[mt][nt], ah[mt][0], ah[mt][1], ah[mt][2], ah[mt][3], bh0, bh1);
                    MMA_TF32(acc[mt][nt], ah[mt][0], ah[mt][1], ah[mt][2], ah[mt][3], bl0, bl1);
                    MMA_TF32(acc[mt][nt], al[mt][0], al[mt][1], al[mt][2], al[mt][3], bh0, bh1);
                }
            }
        }
        __syncthreads();
    }

    #pragma unroll
    for (int mt = 0; mt < 2; mt++) {
        #pragma unroll
        for (int nt = 0; nt < 8; nt++) {
            int row = m0 + wm + mt * 16 + g;
            int col = wn + nt * 8 + 2 * t;
            if (row < M)
                *(float2*)(C + (size_t)row * 128 + col) =
                    make_float2(acc[mt][nt][0], acc[mt][nt][1]);
            if (row + 8 < M)
                *(float2*)(C + (size_t)(row + 8) * 128 + col) =
                    make_float2(acc[mt][nt][2], acc[mt][nt][3]);
        }
    }
}

// ---------------- launch ----------------
// Side stream + events created lazily on the FIRST call (the uncaptured
// correctness call) and reused during graph capture. Cross-stream event
// dependencies become graph edges: CSR build runs concurrently with GEMM1.
extern "C" void kernel_launch(void* const* d_in, const int* in_sizes, int n_in,
                              void* d_out, int out_size) {
    const float* x   = (const float*)d_in[0];
    const int*   src = (const int*)  d_in[1];
    const int*   dst = (const int*)  d_in[2];
    const float* ew  = (const float*)d_in[3];
    const float* W1  = (const float*)d_in[4];
    const float* b1  = (const float*)d_in[5];
    const float* Wmu = (const float*)d_in[6];
    const float* bmu = (const float*)d_in[7];
    const float* Wlv = (const float*)d_in[8];
    const float* blv = (const float*)d_in[9];
    float* out = (float*)d_out;
    const int E = in_sizes[1];

    float *hpre, *h, *hz, *wcat;
    int *cnt, *rowptr, *rank;
    int2 *ep;
    cudaGetSymbolAddress((void**)&hpre,   g_hpre);
    cudaGetSymbolAddress((void**)&h,      g_h);
    cudaGetSymbolAddress((void**)&hz,     g_hz);
    cudaGetSymbolAddress((void**)&wcat,   g_wcat);
    cudaGetSymbolAddress((void**)&cnt,    g_cnt);
    cudaGetSymbolAddress((void**)&rowptr, g_rowptr);
    cudaGetSymbolAddress((void**)&rank,   g_rank);
    cudaGetSymbolAddress((void**)&ep,     g_ep);

    // lazy handles (created on first, uncaptured call; reused thereafter)
    static cudaStream_t s2 = [] {
        cudaStream_t s; cudaStreamCreateWithFlags(&s, cudaStreamNonBlocking); return s;
    }();
    static cudaEvent_t evFork = [] {
        cudaEvent_t e; cudaEventCreateWithFlags(&e, cudaEventDisableTiming); return e;
    }();
    static cudaEvent_t evJoin = [] {
        cudaEvent_t e; cudaEventCreateWithFlags(&e, cudaEventDisableTiming); return e;
    }();

    const int gemm_grid   = (N_NODES + 127) / 128;          // 391
    const int edge_grid   = (E + 255) / 256;
    const int gather_grid = (N_NODES * 32 + 255) / 256;     // warp per node

    // ---- fork: CSR build + weight pack on s2, GEMM1 on main stream ----
    cudaEventRecord(evFork, 0);
    cudaStreamWaitEvent(s2, evFork, 0);

    zero_int   <<<(N_NODES + 255) / 256, 256, 0, s2>>>(cnt, N_NODES);
    hist_kernel<<<edge_grid, 256, 0, s2>>>(dst, cnt, rank, E);
    scan_kernel<<<1, 1024, 0, s2>>>(cnt, rowptr, E);
    fill_kernel<<<edge_grid, 256, 0, s2>>>(src, dst, ew, rank, rowptr, ep, E);
    pack_wcat  <<<64, 256, 0, s2>>>(Wmu, Wlv, wcat);
    cudaEventRecord(evJoin, s2);

    gemm_tf32<<<gemm_grid, 256>>>(x, W1, hpre, N_NODES, NFEAT);   // main stream

    // ---- join ----
    cudaStreamWaitEvent(0, evJoin, 0);

    // Layer 1 aggregation: h = relu(segsum(hpre[src]*w, dst) + b1)
    gather_csr<0><<<gather_grid, 256>>>(hpre, ep, rowptr, b1, nullptr, h);

    // Layer 2: hz = h@[Wmu|Wlv] ; out = segsum(hz[src]*w, dst) + [bmu;blv] split
    gemm_tf32<<<gemm_grid, 256>>>(h, wcat, hz, N_NODES, NHID);
    gather_csr<1><<<gather_grid, 256>>>(hz, ep, rowptr, bmu, blv, out);
}

// round 9
// speedup vs baseline: 2.0588x; 1.0845x over previous
#include <cuda_runtime.h>
#include <cuda_bf16.h>
#include <cuda_fp16.h>
#include <cstdint>

#define N_NODES 50000
#define NFEAT   256
#define NHID    128
#define LATENT  64
#define MAX_E   800000

// ---------------- scratch (no allocations allowed) ----------------
__device__ __half g_hpre[(size_t)N_NODES * NHID];  // x@W1 (layer-1 messages, fp16)
__device__ float  g_h   [(size_t)N_NODES * NHID];  // relu(agg1 + b1)  (fp32, GEMM2 A operand)
__device__ __half g_hz  [(size_t)N_NODES * NHID];  // h@[Wmu|Wlv]      (layer-2 messages, fp16)
__device__ float  g_wcat[NHID * NHID];             // [Wmu | Wlv] packed 128x128
__device__ int    g_cnt [53248];                   // in-degree histogram (padded for int4 scan)
__device__ int    g_rowptr[N_NODES + 1];           // CSR row offsets (by dst)
__device__ int    g_rank[MAX_E];                   // within-bucket rank per edge
__device__ int2   g_ep  [MAX_E];                   // (src, weight-bits) sorted by dst

// ---------------- small utility kernels ----------------
__global__ void zero_int(int* p, int n) {
    int i = blockIdx.x * blockDim.x + threadIdx.x;
    if (i < n) p[i] = 0;
}

__global__ void pack_wcat(const float* __restrict__ Wmu, const float* __restrict__ Wlv,
                          float* __restrict__ Wcat) {
    int i = blockIdx.x * blockDim.x + threadIdx.x;
    if (i >= NHID * NHID) return;
    int k = i >> 7, n = i & 127;
    Wcat[i] = (n < LATENT) ? Wmu[k * LATENT + n] : Wlv[k * LATENT + (n - LATENT)];
}

// ---------------- CSR build ----------------
__global__ void hist_kernel(const int* __restrict__ dst, int* __restrict__ cnt,
                            int* __restrict__ rank, int E) {
    int e = blockIdx.x * blockDim.x + threadIdx.x;
    if (e < E) rank[e] = atomicAdd(&cnt[dst[e]], 1);
}

// single-block scan, int4-vectorized two-pass read
__global__ void scan_kernel(const int* __restrict__ cnt, int* __restrict__ rowptr, int E) {
    __shared__ int sums[1024];
    const int tid = threadIdx.x;
    const int4* c4 = (const int4*)cnt;
    const int b4 = tid * 13;                      // 13 int4 = 52 nodes per thread

    int s = 0;
    #pragma unroll
    for (int i = 0; i < 13; i++) {
        int4 v = c4[b4 + i];
        s += v.x + v.y + v.z + v.w;
    }
    sums[tid] = s;
    __syncthreads();
    #pragma unroll
    for (int d = 1; d < 1024; d <<= 1) {          // Hillis-Steele inclusive
        int add = (tid >= d) ? sums[tid - d] : 0;
        __syncthreads();
        sums[tid] += add;
        __syncthreads();
    }
    int off = sums[tid] - s;                       // exclusive offset
    #pragma unroll
    for (int i = 0; i < 13; i++) {
        int4 v = c4[b4 + i];
        int n = (b4 + i) * 4;
        if (n + 0 < N_NODES) { rowptr[n + 0] = off; off += v.x; }
        if (n + 1 < N_NODES) { rowptr[n + 1] = off; off += v.y; }
        if (n + 2 < N_NODES) { rowptr[n + 2] = off; off += v.z; }
        if (n + 3 < N_NODES) { rowptr[n + 3] = off; off += v.w; }
    }
    if (tid == 0) rowptr[N_NODES] = E;
}

// atomic-free bucket fill using precomputed ranks
__global__ void fill_kernel(const int* __restrict__ src, const int* __restrict__ dst,
                            const float* __restrict__ ew, const int* __restrict__ rank,
                            const int* __restrict__ rowptr, int2* __restrict__ ep, int E) {
    int e = blockIdx.x * blockDim.x + threadIdx.x;
    if (e < E) {
        int p = __ldg(&rowptr[dst[e]]) + rank[e];
        ep[p] = make_int2(src[e], __float_as_int(ew[e]));
    }
}

// ---------------- CSR gather (fp16 messages): one warp per node ----------------
// Lane covers 4 cols (8 B load). Accumulation in fp32.
// MODE 0: out[node,:] = relu(acc + b0)              (layer 1, fp32 out, 128 wide)
// MODE 1: out[:N*64] = acc[:64]+b0 (mu); out[N*64:] = acc[64:]+b1v (logvar)
template<int MODE>
__global__ __launch_bounds__(256) void gather_csr(
    const __half* __restrict__ H, const int2* __restrict__ ep,
    const int* __restrict__ rowptr,
    const float* __restrict__ b0, const float* __restrict__ b1v,
    float* __restrict__ out)
{
    const int node = (blockIdx.x * blockDim.x + threadIdx.x) >> 5;
    const int lane = threadIdx.x & 31;
    if (node >= N_NODES) return;
    const int beg = __ldg(&rowptr[node]);
    const int end = __ldg(&rowptr[node + 1]);
    float4 acc = make_float4(0.f, 0.f, 0.f, 0.f);

    auto fma4 = [&](uint2 v, float w) {
        float2 a = __half22float2(*reinterpret_cast<__half2*>(&v.x));
        float2 b = __half22float2(*reinterpret_cast<__half2*>(&v.y));
        acc.x = fmaf(a.x, w, acc.x); acc.y = fmaf(a.y, w, acc.y);
        acc.z = fmaf(b.x, w, acc.z); acc.w = fmaf(b.y, w, acc.w);
    };

    int j = beg;
    for (; j + 4 <= end; j += 4) {
        int2 e0 = __ldg(&ep[j]);
        int2 e1 = __ldg(&ep[j + 1]);
        int2 e2 = __ldg(&ep[j + 2]);
        int2 e3 = __ldg(&ep[j + 3]);
        uint2 v0 = __ldg((const uint2*)(H + (size_t)e0.x * NHID) + lane);
        uint2 v1 = __ldg((const uint2*)(H + (size_t)e1.x * NHID) + lane);
        uint2 v2 = __ldg((const uint2*)(H + (size_t)e2.x * NHID) + lane);
        uint2 v3 = __ldg((const uint2*)(H + (size_t)e3.x * NHID) + lane);
        fma4(v0, __int_as_float(e0.y));
        fma4(v1, __int_as_float(e1.y));
        fma4(v2, __int_as_float(e2.y));
        fma4(v3, __int_as_float(e3.y));
    }
    for (; j < end; j++) {
        int2 p = __ldg(&ep[j]);
        uint2 v = __ldg((const uint2*)(H + (size_t)p.x * NHID) + lane);
        fma4(v, __int_as_float(p.y));
    }

    if (MODE == 0) {
        float4 b = __ldg((const float4*)b0 + lane);
        acc.x = fmaxf(acc.x + b.x, 0.f);
        acc.y = fmaxf(acc.y + b.y, 0.f);
        acc.z = fmaxf(acc.z + b.z, 0.f);
        acc.w = fmaxf(acc.w + b.w, 0.f);
        *((float4*)(out + (size_t)node * NHID) + lane) = acc;
    } else {
        if (lane < 16) {
            float4 b = __ldg((const float4*)b0 + lane);
            acc.x += b.x; acc.y += b.y; acc.z += b.z; acc.w += b.w;
            *((float4*)(out + (size_t)node * LATENT) + lane) = acc;
        } else {
            float4 b = __ldg((const float4*)b1v + (lane - 16));
            acc.x += b.x; acc.y += b.y; acc.z += b.z; acc.w += b.w;
            *((float4*)(out + (size_t)N_NODES * LATENT + (size_t)node * LATENT) + (lane - 16)) = acc;
        }
    }
}

// ---------------- tf32 tensor-core GEMM, cp.async double-buffered, fp16 out ----------------
// C[M,128] = A[M,K] @ B[K,128]; fp32 in, fp16 out (messages), tf32 hi/lo split at frag load.
__device__ __forceinline__ uint32_t f2tf32(float v) {
    uint32_t r;
    asm("cvt.rna.tf32.f32 %0, %1;" : "=r"(r) : "f"(v));
    return r;
}

__device__ __forceinline__ void cpasync16(void* smem_dst, const void* gsrc) {
    uint32_t d = (uint32_t)__cvta_generic_to_shared(smem_dst);
    asm volatile("cp.async.ca.shared.global [%0], [%1], 16;" :: "r"(d), "l"(gsrc));
}

#define MMA_TF32(c, a0, a1, a2, a3, b0, b1)                                   \
    asm volatile("mma.sync.aligned.m16n8k8.row.col.f32.tf32.tf32.f32 "        \
                 "{%0,%1,%2,%3}, {%4,%5,%6,%7}, {%8,%9}, {%0,%1,%2,%3};"      \
                 : "+f"((c)[0]), "+f"((c)[1]), "+f"((c)[2]), "+f"((c)[3])     \
                 : "r"(a0), "r"(a1), "r"(a2), "r"(a3), "r"(b0), "r"(b1))

#define PADA 20    // row stride 20 floats -> frag LDS conflict-free
#define PADB 136   // 8t+g -> conflict-free

__global__ __launch_bounds__(256) void gemm_tf32(
    const float* __restrict__ A, const float* __restrict__ B, __half* __restrict__ C,
    int M, int K)
{
    __shared__ __align__(16) float As[2][128][PADA];   // raw A, [row][k]
    __shared__ __align__(16) float Bs[2][16][PADB];    // raw B, [k][n]

    const int tid  = threadIdx.x;
    const int wid  = tid >> 5;
    const int lane = tid & 31;
    const int g    = lane >> 2;
    const int t    = lane & 3;
    const int wm   = (wid >> 1) * 32;
    const int wn   = (wid & 1) * 64;
    const int m0   = blockIdx.x * 128;

    float acc[2][8][4] = {};

    auto load_tiles = [&](int s, int k0) {
        #pragma unroll
        for (int it = 0; it < 2; it++) {
            int idx = tid + it * 256;          // 512 float4 slots
            int row = idx >> 2;
            int kk  = (idx & 3) << 2;
            int gr  = m0 + row;
            if (gr >= M) gr = M - 1;           // clamp: junk rows never stored
            cpasync16(&As[s][row][kk], A + (size_t)gr * K + k0 + kk);
        }
        #pragma unroll
        for (int it = 0; it < 2; it++) {
            int idx  = tid + it * 256;
            int krow = idx >> 5;
            int n4   = (idx & 31) << 2;
            cpasync16(&Bs[s][krow][n4], B + (size_t)(k0 + krow) * 128 + n4);
        }
    };

    const int KT = K >> 4;
    load_tiles(0, 0);
    asm volatile("cp.async.commit_group;");

    for (int kt = 0; kt < KT; kt++) {
        const int p = kt & 1;
        if (kt + 1 < KT) {
            load_tiles(p ^ 1, (kt + 1) << 4);
            asm volatile("cp.async.commit_group;");
            asm volatile("cp.async.wait_group 1;");
        } else {
            asm volatile("cp.async.wait_group 0;");
        }
        __syncthreads();

        #pragma unroll
        for (int ks = 0; ks < 16; ks += 8) {
            uint32_t ah[2][4], al[2][4];
            #pragma unroll
            for (int mt = 0; mt < 2; mt++) {
                int mr = wm + mt * 16 + g;
                float ar[4];
                ar[0] = As[p][mr][ks + t];
                ar[1] = As[p][mr + 8][ks + t];
                ar[2] = As[p][mr][ks + t + 4];
                ar[3] = As[p][mr + 8][ks + t + 4];
                #pragma unroll
                for (int q = 0; q < 4; q++) {
                    ah[mt][q] = f2tf32(ar[q]);
                    al[mt][q] = f2tf32(ar[q] - __uint_as_float(ah[mt][q]));
                }
            }
            #pragma unroll
            for (int nt = 0; nt < 8; nt++) {
                int nc = wn + nt * 8 + g;
                float br0 = Bs[p][ks + t][nc];
                float br1 = Bs[p][ks + t + 4][nc];
                uint32_t bh0 = f2tf32(br0);
                uint32_t bl0 = f2tf32(br0 - __uint_as_float(bh0));
                uint32_t bh1 = f2tf32(br1);
                uint32_t bl1 = f2tf32(br1 - __uint_as_float(bh1));
                #pragma unroll
                for (int mt = 0; mt < 2; mt++) {
                    MMA_TF32(acc[mt][nt], ah[mt][0], ah[mt][1], ah[mt][2], ah[mt][3], bh0, bh1);
                    MMA_TF32(acc[mt][nt], ah[mt][0], ah[mt][1], ah[mt][2], ah[mt][3], bl0, bl1);
                    MMA_TF32(acc[mt][nt], al[mt][0], al[mt][1], al[mt][2], al[mt][3], bh0, bh1);
                }
            }
        }
        __syncthreads();
    }

    // --- store as fp16 (half2 per register pair) ---
    #pragma unroll
    for (int mt = 0; mt < 2; mt++) {
        #pragma unroll
        for (int nt = 0; nt < 8; nt++) {
            int row = m0 + wm + mt * 16 + g;
            int col = wn + nt * 8 + 2 * t;
            if (row < M)
                *(__half2*)(C + (size_t)row * 128 + col) =
                    __floats2half2_rn(acc[mt][nt][0], acc[mt][nt][1]);
            if (row + 8 < M)
                *(__half2*)(C + (size_t)(row + 8) * 128 + col) =
                    __floats2half2_rn(acc[mt][nt][2], acc[mt][nt][3]);
        }
    }
}

// ---------------- launch ----------------
// Side stream + events created lazily on the FIRST (uncaptured) call and
// reused during graph capture. CSR build overlaps GEMM1 via fork/join edges.
extern "C" void kernel_launch(void* const* d_in, const int* in_sizes, int n_in,
                              void* d_out, int out_size) {
    const float* x   = (const float*)d_in[0];
    const int*   src = (const int*)  d_in[1];
    const int*   dst = (const int*)  d_in[2];
    const float* ew  = (const float*)d_in[3];
    const float* W1  = (const float*)d_in[4];
    const float* b1  = (const float*)d_in[5];
    const float* Wmu = (const float*)d_in[6];
    const float* bmu = (const float*)d_in[7];
    const float* Wlv = (const float*)d_in[8];
    const float* blv = (const float*)d_in[9];
    float* out = (float*)d_out;
    const int E = in_sizes[1];

    __half *hpre, *hz;
    float *h, *wcat;
    int *cnt, *rowptr, *rank;
    int2 *ep;
    cudaGetSymbolAddress((void**)&hpre,   g_hpre);
    cudaGetSymbolAddress((void**)&h,      g_h);
    cudaGetSymbolAddress((void**)&hz,     g_hz);
    cudaGetSymbolAddress((void**)&wcat,   g_wcat);
    cudaGetSymbolAddress((void**)&cnt,    g_cnt);
    cudaGetSymbolAddress((void**)&rowptr, g_rowptr);
    cudaGetSymbolAddress((void**)&rank,   g_rank);
    cudaGetSymbolAddress((void**)&ep,     g_ep);

    static cudaStream_t s2 = [] {
        cudaStream_t s; cudaStreamCreateWithFlags(&s, cudaStreamNonBlocking); return s;
    }();
    static cudaEvent_t evFork = [] {
        cudaEvent_t e; cudaEventCreateWithFlags(&e, cudaEventDisableTiming); return e;
    }();
    static cudaEvent_t evJoin = [] {
        cudaEvent_t e; cudaEventCreateWithFlags(&e, cudaEventDisableTiming); return e;
    }();

    const int gemm_grid   = (N_NODES + 127) / 128;          // 391
    const int edge_grid   = (E + 255) / 256;
    const int gather_grid = (N_NODES * 32 + 255) / 256;     // warp per node

    // ---- fork: CSR build + weight pack on s2, GEMM1 on main stream ----
    cudaEventRecord(evFork, 0);
    cudaStreamWaitEvent(s2, evFork, 0);

    zero_int   <<<(N_NODES + 255) / 256, 256, 0, s2>>>(cnt, N_NODES);
    hist_kernel<<<edge_grid, 256, 0, s2>>>(dst, cnt, rank, E);
    scan_kernel<<<1, 1024, 0, s2>>>(cnt, rowptr, E);
    fill_kernel<<<edge_grid, 256, 0, s2>>>(src, dst, ew, rank, rowptr, ep, E);
    pack_wcat  <<<64, 256, 0, s2>>>(Wmu, Wlv, wcat);
    cudaEventRecord(evJoin, s2);

    gemm_tf32<<<gemm_grid, 256>>>(x, W1, hpre, N_NODES, NFEAT);   // main stream

    // ---- join ----
    cudaStreamWaitEvent(0, evJoin, 0);

    // Layer 1 aggregation: h = relu(segsum(hpre[src]*w, dst) + b1)   (fp32 out)
    gather_csr<0><<<gather_grid, 256>>>(hpre, ep, rowptr, b1, nullptr, h);

    // Layer 2: hz = h@[Wmu|Wlv] (fp16) ; out = segsum(hz[src]*w, dst) + [bmu;blv]
    gemm_tf32<<<gemm_grid, 256>>>(h, wcat, hz, N_NODES, NHID);
    gather_csr<1><<<gather_grid, 256>>>(hz, ep, rowptr, bmu, blv, out);
}